// round 2
// baseline (speedup 1.0000x reference)
#include <cuda_runtime.h>
#include <math.h>

#define NB     32
#define NPG1   256
#define NFEATD 128
#define NHID   64
#define KP1    128
#define KP2    64
#define NN1    (NB*NPG1)   // 8192
#define NN2    (NB*KP1)    // 4096
#define NN3    (NB*KP2)    // 2048
#define NCLS   6
#define PROJ_MAX 0.996f
#define MINN   1e-15f

// ---------------- device scratch (static globals; no allocation) ----------------
__device__ float g_adj1[NB*NPG1*NPG1];   // 2,097,152
__device__ float g_s[NN1];
__device__ float g_u[NN1*NHID];          // reused across layers
__device__ float g_t1[NN1*NHID];
__device__ float g_dis[NN1];             // reused
__device__ float g_score[NN1];           // reused
__device__ int   g_lidx[NB*KP1];         // reused
__device__ float g_xn1[NN2*NHID];
__device__ float g_a1[NB*KP1];           // reused
__device__ float g_a2[NB*KP1];           // reused
__device__ float g_adj2[NB*KP1*KP1];
__device__ float g_t2[NN2*NHID];
__device__ float g_xn2[NN3*NHID];
__device__ float g_adj3[NB*KP2*KP2];
__device__ float g_t3[NN3*NHID];

// ---------------- helpers ----------------
__device__ __forceinline__ float artanh_(float x){
    x = fminf(fmaxf(x, -1.0f + 1e-7f), 1.0f - 1e-7f);
    return 0.5f*(log1pf(x) - log1pf(-x));
}

// block-wide sum, all threads get result. Works for blockDim 64..256.
__device__ __forceinline__ float blockSum(float v){
    __shared__ float ws[8];
    int lane = threadIdx.x & 31, w = threadIdx.x >> 5;
    int nw = (blockDim.x + 31) >> 5;
    #pragma unroll
    for (int o = 16; o; o >>= 1) v += __shfl_down_sync(0xffffffffu, v, o);
    if (lane == 0) ws[w] = v;
    __syncthreads();
    float r = 0.f;
    for (int i = 0; i < nw; i++) r += ws[i];
    __syncthreads();
    return r;
}

// ---------------- K1: row-sums, zero adj1, to_hyp + HypLinear (layer1) ----------------
__global__ void k_prep1(const float* __restrict__ x, const float* __restrict__ W1,
                        const float* __restrict__ b1, float* __restrict__ adj1,
                        float* __restrict__ s, float* __restrict__ u){
    int n = blockIdx.x, t = threadIdx.x;   // 8192 blocks x 128 threads
    // zero adj1 (8192*256 = full 2,097,152)
    size_t zb = (size_t)n*256 + t;
    adj1[zb] = 0.f; adj1[zb + 128] = 0.f;

    __shared__ float xh[NFEATD];
    float xi = x[(size_t)n*NFEATD + t];
    float ssum = blockSum(xi);
    if (t == 0) s[n] = ssum;

    // to_hyp: expmap0 + proj
    float un = fmaxf(sqrtf(blockSum(xi*xi)), MINN);
    float v  = tanhf(un)*xi/un;
    float nh = fmaxf(sqrtf(blockSum(v*v)), MINN);
    if (nh > PROJ_MAX) v = v/nh*PROJ_MAX;
    xh[t] = v;
    float xnn = fmaxf(sqrtf(blockSum(v*v)), MINN);  // sync also makes xh visible

    // mobius_matvec: mx = xh @ W1^T  (threads < 64)
    float m = 0.f;
    if (t < NHID){
        const float* wr = W1 + (size_t)t*NFEATD;
        #pragma unroll 8
        for (int k = 0; k < NFEATD; k++) m += xh[k]*wr[k];
    }
    float mxn = fmaxf(sqrtf(blockSum(t < NHID ? m*m : 0.f)), MINN);
    float h = (t < NHID) ? tanhf(mxn/xnn*artanh_(xnn))*m/mxn : 0.f;
    float hn = fmaxf(sqrtf(blockSum(h*h)), MINN);
    if (hn > PROJ_MAX) h = h/hn*PROJ_MAX;

    // hb = proj(expmap0(b1))
    float bj = (t < NHID) ? b1[t] : 0.f;
    float bn = fmaxf(sqrtf(blockSum(bj*bj)), MINN);
    float hb = tanhf(bn)*bj/bn;
    float hbn = fmaxf(sqrtf(blockSum(hb*hb)), MINN);
    if (hbn > PROJ_MAX) hb = hb/hbn*PROJ_MAX;

    // mobius_add(h, hb) + proj
    float x2 = blockSum(h*h);
    float y2 = blockSum(hb*hb);
    float xy = blockSum(h*hb);
    float num = (1.f + 2.f*xy + y2)*h + (1.f - x2)*hb;
    float den = fmaxf(1.f + 2.f*xy + x2*y2, MINN);
    float r2 = num/den;
    float rn = fmaxf(sqrtf(blockSum(r2*r2)), MINN);
    if (rn > PROJ_MAX) r2 = r2/rn*PROJ_MAX;

    // logmap0 -> u
    float pn = fmaxf(sqrtf(blockSum(r2*r2)), MINN);
    float uo = artanh_(pn)*r2/pn;
    if (t < NHID) u[(size_t)n*NHID + t] = uo;
}

// ---------------- K2: edge scatter (duplicates write identical values) ----------------
__global__ void k_scatter(const int* __restrict__ ei, int E,
                          const float* __restrict__ s, float* __restrict__ adj){
    int e = blockIdx.x*blockDim.x + threadIdx.x;
    if (e >= E) return;
    int r = ei[e], c = ei[E + e];
    float w = 0.5f*(s[r] + s[c]);
    int g = r >> 8, lr = r & 255, lc = c & 255;
    adj[((size_t)g*NPG1 + lr)*NPG1 + lc] = w;
}

// ---------------- K3: HypAgg + HypAct + logmap0 (generic), also deg->dis ----------------
__global__ void k_agg(const float* __restrict__ adj, const float* __restrict__ u,
                      float* __restrict__ tout, float* __restrict__ dis, int npg){
    __shared__ float row[256];
    int node = blockIdx.x, t = threadIdx.x;       // blockDim 64
    int g = node / npg, r = node - g*npg;
    const float* arow = adj + ((size_t)g*npg + r)*npg;
    float dp = 0.f;
    for (int m = t; m < npg; m += 64){ float a = arow[m]; row[m] = a; dp += a; }
    float deg = blockSum(dp);                      // syncs -> row visible
    if (t == 0) dis[node] = (deg > 0.f) ? 1.0f/sqrtf(deg) : 0.f;

    float acc = 0.f;
    const float* ub = u + (size_t)g*npg*NHID + t;
    for (int m = 0; m < npg; m++) acc += row[m]*ub[(size_t)m*NHID];

    // expmap0, proj, logmap0, relu, expmap0, proj, logmap0
    float v = acc;
    float un = fmaxf(sqrtf(blockSum(v*v)), MINN);  v = tanhf(un)*v/un;
    float nh = fmaxf(sqrtf(blockSum(v*v)), MINN);  if (nh > PROJ_MAX) v = v/nh*PROJ_MAX;
    float pn = fmaxf(sqrtf(blockSum(v*v)), MINN);  v = artanh_(pn)*v/pn;
    v = fmaxf(v, 0.f);
    float un2 = fmaxf(sqrtf(blockSum(v*v)), MINN); v = tanhf(un2)*v/un2;
    float nh2 = fmaxf(sqrtf(blockSum(v*v)), MINN); if (nh2 > PROJ_MAX) v = v/nh2*PROJ_MAX;
    float pn2 = fmaxf(sqrtf(blockSum(v*v)), MINN); v = artanh_(pn2)*v/pn2;
    tout[(size_t)node*NHID + t] = v;
}

// ---------------- K4: node information score ----------------
__global__ void k_score(const float* __restrict__ adj, const float* __restrict__ tin,
                        const float* __restrict__ dis, float* __restrict__ score, int npg){
    __shared__ float row[256];
    int node = blockIdx.x, t = threadIdx.x;       // blockDim 64
    int g = node / npg, r = node - g*npg;
    const float* arow = adj + ((size_t)g*npg + r)*npg;
    const float* disg = dis + (size_t)g*npg;
    for (int m = t; m < npg; m += 64) row[m] = arow[m]*disg[m];
    __syncthreads();
    float acc = 0.f;
    const float* tb = tin + (size_t)g*npg*NHID + t;
    for (int m = 0; m < npg; m++) acc += row[m]*tb[(size_t)m*NHID];
    float prop = dis[node]*acc;
    float d = fabsf(tin[(size_t)node*NHID + t] - prop);
    float sc = blockSum(d);
    if (t == 0) score[node] = sc;
}

// ---------------- K5: per-graph top-k (bitonic), xn = t[sel]*tanh(val), att dots ----------------
__global__ void k_topk(const float* __restrict__ score, const float* __restrict__ tin,
                       const float* __restrict__ att, int* __restrict__ lidx,
                       float* __restrict__ xn, float* __restrict__ a1, float* __restrict__ a2,
                       int npg, int k){
    __shared__ float key[256];
    __shared__ int   idx[256];
    int g = blockIdx.x, t = threadIdx.x;          // blockDim == npg (pow2)
    key[t] = score[g*npg + t]; idx[t] = t;
    for (int size = 2; size <= npg; size <<= 1){
        for (int stride = size >> 1; stride > 0; stride >>= 1){
            __syncthreads();
            int p = t ^ stride;
            if (p > t){
                float ka = key[t], kb = key[p];
                int ia = idx[t], ib = idx[p];
                bool before = (ka > kb) || (ka == kb && ia < ib); // a ranks first (desc)
                bool desc = ((t & size) == 0);
                if (desc ? !before : before){
                    key[t] = kb; key[p] = ka; idx[t] = ib; idx[p] = ia;
                }
            }
        }
    }
    __syncthreads();
    if (t < k){
        int li = idx[t];
        lidx[g*k + t] = li;
        float tv = tanhf(key[t]);
        const float* src = tin + ((size_t)g*npg + li)*NHID;
        float* dst = xn + ((size_t)g*k + t)*NHID;
        float d1 = 0.f, d2 = 0.f;
        for (int j = 0; j < NHID; j++){
            float v = src[j]*tv; dst[j] = v;
            d1 += v*att[j]; d2 += v*att[NHID + j];
        }
        a1[g*k + t] = d1; a2[g*k + t] = d2;
    }
}

// ---------------- K6: structure learning -> new adjacency ----------------
__global__ void k_adjbuild(const float* __restrict__ a1, const float* __restrict__ a2,
                           const int* __restrict__ lidx, const float* __restrict__ oldadj,
                           float* __restrict__ newadj, int npg, int k){
    int bi = blockIdx.x;           // g*k + i
    int g = bi / k, i = bi - g*k;
    int j = threadIdx.x;           // blockDim == k
    float e = a1[g*k + i] + a2[g*k + j];
    float lr = (e > 0.f) ? e : 0.2f*e;
    float re = fmaxf(lr, 0.f);
    int li = lidx[g*k + i], lj = lidx[g*k + j];
    newadj[((size_t)g*k + i)*k + j] = re + oldadj[((size_t)g*npg + li)*npg + lj];
}

// ---------------- K7: to_hyp + HypLinear for 64-dim layers ----------------
__global__ void k_linear(const float* __restrict__ xin, const float* __restrict__ W,
                         const float* __restrict__ b, float* __restrict__ u){
    __shared__ float xh[NHID];
    int n = blockIdx.x, t = threadIdx.x;          // blockDim 64
    float xi = xin[(size_t)n*NHID + t];
    float un = fmaxf(sqrtf(blockSum(xi*xi)), MINN);
    float v  = tanhf(un)*xi/un;
    float nh = fmaxf(sqrtf(blockSum(v*v)), MINN);
    if (nh > PROJ_MAX) v = v/nh*PROJ_MAX;
    xh[t] = v;
    float xnn = fmaxf(sqrtf(blockSum(v*v)), MINN);
    float m = 0.f;
    const float* wr = W + (size_t)t*NHID;
    #pragma unroll 8
    for (int k = 0; k < NHID; k++) m += xh[k]*wr[k];
    float mxn = fmaxf(sqrtf(blockSum(m*m)), MINN);
    float h = tanhf(mxn/xnn*artanh_(xnn))*m/mxn;
    float hn = fmaxf(sqrtf(blockSum(h*h)), MINN);
    if (hn > PROJ_MAX) h = h/hn*PROJ_MAX;
    float bj = b[t];
    float bn = fmaxf(sqrtf(blockSum(bj*bj)), MINN);
    float hb = tanhf(bn)*bj/bn;
    float hbn = fmaxf(sqrtf(blockSum(hb*hb)), MINN);
    if (hbn > PROJ_MAX) hb = hb/hbn*PROJ_MAX;
    float x2 = blockSum(h*h), y2 = blockSum(hb*hb), xy = blockSum(h*hb);
    float num = (1.f + 2.f*xy + y2)*h + (1.f - x2)*hb;
    float den = fmaxf(1.f + 2.f*xy + x2*y2, MINN);
    float r2 = num/den;
    float rn = fmaxf(sqrtf(blockSum(r2*r2)), MINN);
    if (rn > PROJ_MAX) r2 = r2/rn*PROJ_MAX;
    float pn = fmaxf(sqrtf(blockSum(r2*r2)), MINN);
    u[(size_t)n*NHID + t] = artanh_(pn)*r2/pn;
}

// ---------------- K8: readouts + MLP head + log_softmax ----------------
__global__ void k_final(const float* __restrict__ xn1, const float* __restrict__ xn2,
                        const float* __restrict__ t3,
                        const float* __restrict__ lw1, const float* __restrict__ lb1,
                        const float* __restrict__ lw2, const float* __restrict__ lb2,
                        const float* __restrict__ lw3, const float* __restrict__ lb3,
                        float* __restrict__ out){
    __shared__ float rr[2*NHID];
    __shared__ float h1[NHID];
    __shared__ float h2[NHID/2];
    __shared__ float lg[NCLS];
    int g = blockIdx.x, t = threadIdx.x;          // 32 blocks x 128 threads
    bool ismax = t < NHID;
    int f = ismax ? t : t - NHID;
    float v1, v2, v3;
    {
        const float* base = xn1 + (size_t)g*KP1*NHID + f;
        if (ismax){ float mx = -3.402823466e38f; for (int i = 0; i < KP1; i++) mx = fmaxf(mx, base[(size_t)i*NHID]); v1 = mx; }
        else      { float sm = 0.f;              for (int i = 0; i < KP1; i++) sm += base[(size_t)i*NHID]; v1 = sm/(float)KP1; }
    }
    {
        const float* base = xn2 + (size_t)g*KP2*NHID + f;
        if (ismax){ float mx = -3.402823466e38f; for (int i = 0; i < KP2; i++) mx = fmaxf(mx, base[(size_t)i*NHID]); v2 = mx; }
        else      { float sm = 0.f;              for (int i = 0; i < KP2; i++) sm += base[(size_t)i*NHID]; v2 = sm/(float)KP2; }
    }
    {
        const float* base = t3 + (size_t)g*KP2*NHID + f;
        if (ismax){ float mx = -3.402823466e38f; for (int i = 0; i < KP2; i++) mx = fmaxf(mx, base[(size_t)i*NHID]); v3 = mx; }
        else      { float sm = 0.f;              for (int i = 0; i < KP2; i++) sm += base[(size_t)i*NHID]; v3 = sm/(float)KP2; }
    }
    rr[t] = fmaxf(v1, 0.f) + fmaxf(v2, 0.f) + fmaxf(v3, 0.f);
    __syncthreads();
    if (t < NHID){
        float a = lb1[t];
        for (int q = 0; q < 2*NHID; q++) a += lw1[(size_t)t*2*NHID + q]*rr[q];
        h1[t] = fmaxf(a, 0.f);
    }
    __syncthreads();
    if (t < NHID/2){
        float a = lb2[t];
        for (int q = 0; q < NHID; q++) a += lw2[(size_t)t*NHID + q]*h1[q];
        h2[t] = fmaxf(a, 0.f);
    }
    __syncthreads();
    if (t < NCLS){
        float a = lb3[t];
        for (int q = 0; q < NHID/2; q++) a += lw3[(size_t)t*(NHID/2) + q]*h2[q];
        lg[t] = a;
    }
    __syncthreads();
    if (t == 0){
        float mx = lg[0];
        for (int c = 1; c < NCLS; c++) mx = fmaxf(mx, lg[c]);
        float sm = 0.f;
        for (int c = 0; c < NCLS; c++) sm += expf(lg[c] - mx);
        float lse = mx + logf(sm);
        for (int c = 0; c < NCLS; c++) out[g*NCLS + c] = lg[c] - lse;
    }
}

// ---------------- host launcher ----------------
extern "C" void kernel_launch(void* const* d_in, const int* in_sizes, int n_in,
                              void* d_out, int out_size){
    const float* x    = (const float*)d_in[0];
    const int*   ei   = (const int*)  d_in[1];
    const float* W1   = (const float*)d_in[2];
    const float* b1   = (const float*)d_in[3];
    const float* W2   = (const float*)d_in[4];
    const float* b2   = (const float*)d_in[5];
    const float* W3   = (const float*)d_in[6];
    const float* b3   = (const float*)d_in[7];
    const float* att1 = (const float*)d_in[8];
    const float* att2 = (const float*)d_in[9];
    const float* lw1  = (const float*)d_in[10];
    const float* lb1  = (const float*)d_in[11];
    const float* lw2  = (const float*)d_in[12];
    const float* lb2  = (const float*)d_in[13];
    const float* lw3  = (const float*)d_in[14];
    const float* lb3  = (const float*)d_in[15];
    float* out = (float*)d_out;
    int E = in_sizes[1]/2;

    float *adj1, *s, *u, *t1, *dis, *score, *xn1, *a1, *a2, *adj2, *t2, *xn2, *adj3, *t3;
    int* lidx;
    cudaGetSymbolAddress((void**)&adj1,  g_adj1);
    cudaGetSymbolAddress((void**)&s,     g_s);
    cudaGetSymbolAddress((void**)&u,     g_u);
    cudaGetSymbolAddress((void**)&t1,    g_t1);
    cudaGetSymbolAddress((void**)&dis,   g_dis);
    cudaGetSymbolAddress((void**)&score, g_score);
    cudaGetSymbolAddress((void**)&lidx,  g_lidx);
    cudaGetSymbolAddress((void**)&xn1,   g_xn1);
    cudaGetSymbolAddress((void**)&a1,    g_a1);
    cudaGetSymbolAddress((void**)&a2,    g_a2);
    cudaGetSymbolAddress((void**)&adj2,  g_adj2);
    cudaGetSymbolAddress((void**)&t2,    g_t2);
    cudaGetSymbolAddress((void**)&xn2,   g_xn2);
    cudaGetSymbolAddress((void**)&adj3,  g_adj3);
    cudaGetSymbolAddress((void**)&t3,    g_t3);

    // layer 1
    k_prep1  <<<NN1, 128>>>(x, W1, b1, adj1, s, u);
    k_scatter<<<(E + 255)/256, 256>>>(ei, E, s, adj1);
    k_agg    <<<NN1, 64>>>(adj1, u, t1, dis, NPG1);
    k_score  <<<NN1, 64>>>(adj1, t1, dis, score, NPG1);
    k_topk   <<<NB, NPG1>>>(score, t1, att1, lidx, xn1, a1, a2, NPG1, KP1);
    k_adjbuild<<<NB*KP1, KP1>>>(a1, a2, lidx, adj1, adj2, NPG1, KP1);
    // layer 2
    k_linear <<<NN2, 64>>>(xn1, W2, b2, u);
    k_agg    <<<NN2, 64>>>(adj2, u, t2, dis, KP1);
    k_score  <<<NN2, 64>>>(adj2, t2, dis, score, KP1);
    k_topk   <<<NB, KP1>>>(score, t2, att2, lidx, xn2, a1, a2, KP1, KP2);
    k_adjbuild<<<NB*KP2, KP2>>>(a1, a2, lidx, adj2, adj3, KP1, KP2);
    // layer 3
    k_linear <<<NN3, 64>>>(xn2, W3, b3, u);
    k_agg    <<<NN3, 64>>>(adj3, u, t3, dis, KP2);
    // readout + MLP
    k_final  <<<NB, 128>>>(xn1, xn2, t3, lw1, lb1, lw2, lb2, lw3, lb3, out);
}

// round 3
// speedup vs baseline: 2.5794x; 2.5794x over previous
#include <cuda_runtime.h>
#include <math.h>

#define NB     32
#define NPG1   256
#define NFEATD 128
#define NHID   64
#define KP1    128
#define KP2    64
#define NN1    (NB*NPG1)   // 8192
#define NN2    (NB*KP1)    // 4096
#define NN3    (NB*KP2)    // 2048
#define NCLS   6
#define PROJ_MAX 0.996f
#define MINN   1e-15f
#define AART   3.1063030f   // artanh(0.996)

// ---------------- device scratch ----------------
__device__ float g_adj1[NB*NPG1*NPG1];
__device__ float g_s[NN1];
__device__ float g_u[NN1*NHID];
__device__ float g_t1[NN1*NHID];
__device__ float g_dis[NN1];
__device__ float g_score[NN1];
__device__ int   g_lidx[NB*KP1];
__device__ float g_xn1[NN2*NHID];
__device__ float g_a1[NB*KP1];
__device__ float g_a2[NB*KP1];
__device__ float g_adj2[NB*KP1*KP1];
__device__ float g_t2[NN2*NHID];
__device__ float g_xn2[NN3*NHID];
__device__ float g_adj3[NB*KP2*KP2];
__device__ float g_t3[NN3*NHID];

// ---------------- helpers ----------------
__device__ __forceinline__ float artanh_(float x){
    x = fminf(fmaxf(x, -1.0f + 1e-7f), 1.0f - 1e-7f);
    return 0.5f*(log1pf(x) - log1pf(-x));
}
__device__ __forceinline__ float warpSum(float v){
    #pragma unroll
    for (int o = 16; o; o >>= 1) v += __shfl_xor_sync(0xffffffffu, v, o);
    return v;
}

// mobius tail shared by linear kernels: input mx (64-dim split across lanes), xn=||xh||.
// writes u = logmap0(proj(mobius_add(proj(matvec_result), hb)))
__device__ __forceinline__ void hyp_tail(float mx0, float mx1, float xn,
                                         const float* __restrict__ bb, int l,
                                         float* __restrict__ up){
    float mxn = fmaxf(sqrtf(warpSum(mx0*mx0 + mx1*mx1)), MINN);
    float tv  = tanhf(mxn/xn*artanh_(xn));          // >= 0
    float hs  = tv/mxn;
    float h0 = mx0*hs, h1 = mx1*hs;
    float hn = tv;
    if (hn > PROJ_MAX){ float c = PROJ_MAX/hn; h0 *= c; h1 *= c; hn = PROJ_MAX; }
    float x2 = hn*hn;
    float b0 = bb[l], b1 = bb[l+32];
    float bn = fmaxf(sqrtf(warpSum(b0*b0 + b1*b1)), MINN);
    float tb = tanhf(bn);
    float hbs = tb/bn, hbn = tb;
    if (tb > PROJ_MAX){ hbs = PROJ_MAX/bn; hbn = PROJ_MAX; }
    float hb0 = b0*hbs, hb1 = b1*hbs;
    float y2 = hbn*hbn;
    float xy = warpSum(h0*hb0 + h1*hb1);
    float ca = 1.f + 2.f*xy + y2, cb = 1.f - x2;
    float den = fmaxf(1.f + 2.f*xy + x2*y2, MINN);
    float r0 = (ca*h0 + cb*hb0)/den, r1 = (ca*h1 + cb*hb1)/den;
    float rn = fmaxf(sqrtf(warpSum(r0*r0 + r1*r1)), MINN);
    float pn = rn, psc = 1.f;
    if (rn > PROJ_MAX){ psc = PROJ_MAX/rn; pn = PROJ_MAX; }
    float ls = artanh_(pn)/pn*psc;
    up[l] = r0*ls; up[l+32] = r1*ls;
}

// ---------------- K1: zero adj1 + row sums + to_hyp + HypLinear (layer1) ----------------
// grid 1024 x 256 (8 warps = 8 nodes per block)
__global__ void k_prep1(const float* __restrict__ x, const float* __restrict__ W1,
                        const float* __restrict__ bb, float* __restrict__ adj1,
                        float* __restrict__ s, float* __restrict__ u){
    __shared__ float Wt[128*64];
    int tid = threadIdx.x;
    {   // zero this block's 2048-float slice of adj1
        float4 z = make_float4(0.f,0.f,0.f,0.f);
        float4* pz = (float4*)(adj1 + (size_t)blockIdx.x*2048);
        pz[tid] = z; pz[tid + 256] = z;
    }
    for (int e = tid; e < 128*64; e += 256){
        int j = e >> 7, k = e & 127;
        Wt[k*64 + j] = W1[e];
    }
    __syncthreads();
    int w = tid >> 5, l = tid & 31;
    int node = blockIdx.x*8 + w;
    const float* xp = x + (size_t)node*128;
    float xq[4];
    #pragma unroll
    for (int q = 0; q < 4; q++) xq[q] = xp[l + 32*q];
    float ssum = warpSum(xq[0]+xq[1]+xq[2]+xq[3]);
    if (l == 0) s[node] = ssum;
    float n0 = fmaxf(sqrtf(warpSum(xq[0]*xq[0]+xq[1]*xq[1]+xq[2]*xq[2]+xq[3]*xq[3])), MINN);
    float th = tanhf(n0);
    float xsc, xn;
    if (th > PROJ_MAX){ xsc = PROJ_MAX/n0; xn = PROJ_MAX; } else { xsc = th/n0; xn = th; }
    xn = fmaxf(xn, MINN);
    #pragma unroll
    for (int q = 0; q < 4; q++) xq[q] *= xsc;
    float mx0 = 0.f, mx1 = 0.f;
    #pragma unroll
    for (int q = 0; q < 4; q++){
        float xv = xq[q];
        for (int kk = 0; kk < 32; kk++){
            float xk = __shfl_sync(0xffffffffu, xv, kk);
            int k = q*32 + kk;
            mx0 += xk*Wt[k*64 + l];
            mx1 += xk*Wt[k*64 + l + 32];
        }
    }
    hyp_tail(mx0, mx1, xn, bb, l, u + (size_t)node*64);
}

// ---------------- K7: to_hyp + HypLinear, 64-dim ----------------
__global__ void k_linear(const float* __restrict__ xin, const float* __restrict__ W,
                         const float* __restrict__ bb, float* __restrict__ u){
    __shared__ float Wt[64*64];
    int tid = threadIdx.x;
    for (int e = tid; e < 4096; e += 256){
        int j = e >> 6, k = e & 63;
        Wt[k*64 + j] = W[e];
    }
    __syncthreads();
    int w = tid >> 5, l = tid & 31;
    int node = blockIdx.x*8 + w;
    const float* xp = xin + (size_t)node*64;
    float x0 = xp[l], x1 = xp[l+32];
    float n0 = fmaxf(sqrtf(warpSum(x0*x0 + x1*x1)), MINN);
    float th = tanhf(n0);
    float xsc, xn;
    if (th > PROJ_MAX){ xsc = PROJ_MAX/n0; xn = PROJ_MAX; } else { xsc = th/n0; xn = th; }
    xn = fmaxf(xn, MINN);
    x0 *= xsc; x1 *= xsc;
    float mx0 = 0.f, mx1 = 0.f;
    #pragma unroll
    for (int q = 0; q < 2; q++){
        float xv = q ? x1 : x0;
        for (int kk = 0; kk < 32; kk++){
            float xk = __shfl_sync(0xffffffffu, xv, kk);
            int k = q*32 + kk;
            mx0 += xk*Wt[k*64 + l];
            mx1 += xk*Wt[k*64 + l + 32];
        }
    }
    hyp_tail(mx0, mx1, xn, bb, l, u + (size_t)node*64);
}

// ---------------- K2: edge scatter ----------------
__global__ void k_scatter(const int* __restrict__ ei, int E,
                          const float* __restrict__ s, float* __restrict__ adj){
    int e = blockIdx.x*blockDim.x + threadIdx.x;
    if (e >= E) return;
    int r = ei[e], c = ei[E + e];
    float w = 0.5f*(s[r] + s[c]);
    int g = r >> 8, lr = r & 255, lc = c & 255;
    adj[((size_t)g*NPG1 + lr)*NPG1 + lc] = w;
}

// ---------------- K3: tiled HypAgg (+deg->dis). out = logmap-collapsed chain ----------------
__device__ __forceinline__ void agg_epi(int node, float a0, float a1, float deg,
                                        float* __restrict__ tout, float* __restrict__ dis, int l){
    float n1 = sqrtf(warpSum(a0*a0 + a1*a1));
    float s1 = (n1 > AART) ? AART/n1 : 1.f;
    float w0 = fmaxf(a0*s1, 0.f), w1 = fmaxf(a1*s1, 0.f);
    float n2 = sqrtf(warpSum(w0*w0 + w1*w1));
    float s2 = (n2 > AART) ? AART/n2 : 1.f;
    tout[(size_t)node*64 + l]      = w0*s2;
    tout[(size_t)node*64 + l + 32] = w1*s2;
    if (l == 0) dis[node] = (deg > 0.f) ? rsqrtf(deg) : 0.f;
}

template<int NPG>
__global__ void k_aggT(const float* __restrict__ adj, const float* __restrict__ u,
                       float* __restrict__ tout, float* __restrict__ dis){
    constexpr int CH = (NPG < 128) ? NPG : 128;
    __shared__ float ush[CH*64];
    constexpr int TPG = NPG/32;
    int g = blockIdx.x / TPG, rtile = blockIdx.x % TPG;
    int w = threadIdx.x >> 5, l = threadIdx.x & 31;
    int rbase = rtile*32 + w*4;
    const float* adjg = adj + (size_t)g*NPG*NPG;
    const float* ug   = u   + (size_t)g*NPG*64;
    float a00=0,a01=0,a10=0,a11=0,a20=0,a21=0,a30=0,a31=0;
    float d0=0,d1=0,d2=0,d3=0;
    for (int c0 = 0; c0 < NPG; c0 += CH){
        __syncthreads();
        const float4* src = (const float4*)(ug + (size_t)c0*64);
        float4* dst = (float4*)ush;
        for (int e = threadIdx.x; e < CH*16; e += 256) dst[e] = src[e];
        __syncthreads();
        const float* r0p = adjg + (size_t)(rbase+0)*NPG + c0;
        const float* r1p = adjg + (size_t)(rbase+1)*NPG + c0;
        const float* r2p = adjg + (size_t)(rbase+2)*NPG + c0;
        const float* r3p = adjg + (size_t)(rbase+3)*NPG + c0;
        #pragma unroll 2
        for (int m = 0; m < CH; m += 4){
            float4 v0 = *(const float4*)(r0p + m);
            float4 v1 = *(const float4*)(r1p + m);
            float4 v2 = *(const float4*)(r2p + m);
            float4 v3 = *(const float4*)(r3p + m);
            float ar0[4] = {v0.x, v0.y, v0.z, v0.w};
            float ar1[4] = {v1.x, v1.y, v1.z, v1.w};
            float ar2[4] = {v2.x, v2.y, v2.z, v2.w};
            float ar3[4] = {v3.x, v3.y, v3.z, v3.w};
            #pragma unroll
            for (int q = 0; q < 4; q++){
                float u0 = ush[(m+q)*64 + l];
                float u1 = ush[(m+q)*64 + l + 32];
                a00 += ar0[q]*u0; a01 += ar0[q]*u1; d0 += ar0[q];
                a10 += ar1[q]*u0; a11 += ar1[q]*u1; d1 += ar1[q];
                a20 += ar2[q]*u0; a21 += ar2[q]*u1; d2 += ar2[q];
                a30 += ar3[q]*u0; a31 += ar3[q]*u1; d3 += ar3[q];
            }
        }
    }
    int nb = g*NPG + rbase;
    agg_epi(nb+0, a00, a01, d0, tout, dis, l);
    agg_epi(nb+1, a10, a11, d1, tout, dis, l);
    agg_epi(nb+2, a20, a21, d2, tout, dis, l);
    agg_epi(nb+3, a30, a31, d3, tout, dis, l);
}

// ---------------- K4: tiled node information score ----------------
template<int NPG>
__global__ void k_scoreT(const float* __restrict__ adj, const float* __restrict__ t,
                         const float* __restrict__ dis, float* __restrict__ score){
    constexpr int CH = (NPG < 128) ? NPG : 128;
    __shared__ float tsh[CH*64];
    constexpr int TPG = NPG/32;
    int g = blockIdx.x / TPG, rtile = blockIdx.x % TPG;
    int w = threadIdx.x >> 5, l = threadIdx.x & 31;
    int rbase = rtile*32 + w*4;
    const float* adjg = adj + (size_t)g*NPG*NPG;
    const float* tg   = t   + (size_t)g*NPG*64;
    const float* disg = dis + (size_t)g*NPG;
    float tr[4][2], dr[4];
    #pragma unroll
    for (int i = 0; i < 4; i++){
        tr[i][0] = tg[(size_t)(rbase+i)*64 + l];
        tr[i][1] = tg[(size_t)(rbase+i)*64 + l + 32];
        dr[i]    = disg[rbase+i];
    }
    float a00=0,a01=0,a10=0,a11=0,a20=0,a21=0,a30=0,a31=0;
    for (int c0 = 0; c0 < NPG; c0 += CH){
        __syncthreads();
        const float4* src = (const float4*)(tg + (size_t)c0*64);
        float4* dst = (float4*)tsh;
        for (int e = threadIdx.x; e < CH*16; e += 256){
            float4 v = src[e];
            float dm = disg[c0 + (e >> 4)];
            v.x *= dm; v.y *= dm; v.z *= dm; v.w *= dm;
            dst[e] = v;
        }
        __syncthreads();
        const float* r0p = adjg + (size_t)(rbase+0)*NPG + c0;
        const float* r1p = adjg + (size_t)(rbase+1)*NPG + c0;
        const float* r2p = adjg + (size_t)(rbase+2)*NPG + c0;
        const float* r3p = adjg + (size_t)(rbase+3)*NPG + c0;
        #pragma unroll 2
        for (int m = 0; m < CH; m += 4){
            float4 v0 = *(const float4*)(r0p + m);
            float4 v1 = *(const float4*)(r1p + m);
            float4 v2 = *(const float4*)(r2p + m);
            float4 v3 = *(const float4*)(r3p + m);
            float ar0[4] = {v0.x, v0.y, v0.z, v0.w};
            float ar1[4] = {v1.x, v1.y, v1.z, v1.w};
            float ar2[4] = {v2.x, v2.y, v2.z, v2.w};
            float ar3[4] = {v3.x, v3.y, v3.z, v3.w};
            #pragma unroll
            for (int q = 0; q < 4; q++){
                float u0 = tsh[(m+q)*64 + l];
                float u1 = tsh[(m+q)*64 + l + 32];
                a00 += ar0[q]*u0; a01 += ar0[q]*u1;
                a10 += ar1[q]*u0; a11 += ar1[q]*u1;
                a20 += ar2[q]*u0; a21 += ar2[q]*u1;
                a30 += ar3[q]*u0; a31 += ar3[q]*u1;
            }
        }
    }
    float acc0[4] = {a00,a10,a20,a30}, acc1[4] = {a01,a11,a21,a31};
    #pragma unroll
    for (int i = 0; i < 4; i++){
        float d = fabsf(tr[i][0] - dr[i]*acc0[i]) + fabsf(tr[i][1] - dr[i]*acc1[i]);
        float sc = warpSum(d);
        if (l == 0) score[g*NPG + rbase + i] = sc;
    }
}

// ---------------- K5: per-graph top-k (bitonic) + xn + att dots ----------------
__global__ void k_topk(const float* __restrict__ score, const float* __restrict__ tin,
                       const float* __restrict__ att, int* __restrict__ lidx,
                       float* __restrict__ xn, float* __restrict__ a1, float* __restrict__ a2,
                       int npg, int k){
    __shared__ float key[256];
    __shared__ int   idx[256];
    int g = blockIdx.x, t = threadIdx.x;          // blockDim == npg (pow2)
    key[t] = score[g*npg + t]; idx[t] = t;
    for (int size = 2; size <= npg; size <<= 1){
        for (int stride = size >> 1; stride > 0; stride >>= 1){
            __syncthreads();
            int p = t ^ stride;
            if (p > t){
                float ka = key[t], kb = key[p];
                int ia = idx[t], ib = idx[p];
                bool before = (ka > kb) || (ka == kb && ia < ib);
                bool desc = ((t & size) == 0);
                if (desc ? !before : before){
                    key[t] = kb; key[p] = ka; idx[t] = ib; idx[p] = ia;
                }
            }
        }
    }
    __syncthreads();
    if (t < k){
        int li = idx[t];
        lidx[g*k + t] = li;
        float tv = tanhf(key[t]);
        const float* src = tin + ((size_t)g*npg + li)*NHID;
        float* dst = xn + ((size_t)g*k + t)*NHID;
        float d1 = 0.f, d2 = 0.f;
        for (int j = 0; j < NHID; j++){
            float v = src[j]*tv; dst[j] = v;
            d1 += v*att[j]; d2 += v*att[NHID + j];
        }
        a1[g*k + t] = d1; a2[g*k + t] = d2;
    }
}

// ---------------- K6: structure learning -> new adjacency ----------------
__global__ void k_adjbuild(const float* __restrict__ a1, const float* __restrict__ a2,
                           const int* __restrict__ lidx, const float* __restrict__ oldadj,
                           float* __restrict__ newadj, int npg, int k){
    int bi = blockIdx.x;
    int g = bi / k, i = bi - g*k;
    int j = threadIdx.x;
    float e = a1[g*k + i] + a2[g*k + j];
    float lr = (e > 0.f) ? e : 0.2f*e;
    float re = fmaxf(lr, 0.f);
    int li = lidx[g*k + i], lj = lidx[g*k + j];
    newadj[((size_t)g*k + i)*k + j] = re + oldadj[((size_t)g*npg + li)*npg + lj];
}

// ---------------- K8: readouts + MLP head + log_softmax ----------------
__global__ void k_final(const float* __restrict__ xn1, const float* __restrict__ xn2,
                        const float* __restrict__ t3,
                        const float* __restrict__ lw1, const float* __restrict__ lb1,
                        const float* __restrict__ lw2, const float* __restrict__ lb2,
                        const float* __restrict__ lw3, const float* __restrict__ lb3,
                        float* __restrict__ out){
    __shared__ float sA[4*64], sB[4*64], rr[128], h1[64], h2[32], lg[NCLS];
    int g = blockIdx.x, t = threadIdx.x;
    int f = t & 63, grp = t >> 6;
    float accM = 0.f, accE = 0.f;
    #pragma unroll
    for (int srci = 0; srci < 3; srci++){
        const float* base = (srci == 0) ? xn1 + (size_t)g*KP1*64
                          : (srci == 1) ? xn2 + (size_t)g*KP2*64
                                        : t3  + (size_t)g*KP2*64;
        int K = (srci == 0) ? KP1 : KP2;
        float pm = -3.402823466e38f, ps = 0.f;
        for (int i = grp; i < K; i += 4){
            float v = base[(size_t)i*64 + f];
            pm = fmaxf(pm, v); ps += v;
        }
        sA[grp*64 + f] = pm; sB[grp*64 + f] = ps;
        __syncthreads();
        if (t < 64){
            float mx = fmaxf(fmaxf(sA[f], sA[64+f]), fmaxf(sA[128+f], sA[192+f]));
            float sm = sB[f] + sB[64+f] + sB[128+f] + sB[192+f];
            accM += fmaxf(mx, 0.f);
            accE += fmaxf(sm/(float)K, 0.f);
        }
        __syncthreads();
    }
    if (t < 64){ rr[f] = accM; rr[64+f] = accE; }
    __syncthreads();
    if (t < 64){
        float a = lb1[t];
        #pragma unroll 8
        for (int q = 0; q < 128; q++) a += lw1[(size_t)t*128 + q]*rr[q];
        h1[t] = fmaxf(a, 0.f);
    }
    __syncthreads();
    if (t < 32){
        float a = lb2[t];
        #pragma unroll 8
        for (int q = 0; q < 64; q++) a += lw2[(size_t)t*64 + q]*h1[q];
        h2[t] = fmaxf(a, 0.f);
    }
    __syncthreads();
    if (t < NCLS){
        float a = lb3[t];
        #pragma unroll
        for (int q = 0; q < 32; q++) a += lw3[(size_t)t*32 + q]*h2[q];
        lg[t] = a;
    }
    __syncthreads();
    if (t == 0){
        float mx = lg[0];
        for (int c = 1; c < NCLS; c++) mx = fmaxf(mx, lg[c]);
        float sm = 0.f;
        for (int c = 0; c < NCLS; c++) sm += expf(lg[c] - mx);
        float lse = mx + logf(sm);
        for (int c = 0; c < NCLS; c++) out[g*NCLS + c] = lg[c] - lse;
    }
}

// ---------------- host launcher ----------------
extern "C" void kernel_launch(void* const* d_in, const int* in_sizes, int n_in,
                              void* d_out, int out_size){
    const float* x    = (const float*)d_in[0];
    const int*   ei   = (const int*)  d_in[1];
    const float* W1   = (const float*)d_in[2];
    const float* b1   = (const float*)d_in[3];
    const float* W2   = (const float*)d_in[4];
    const float* b2   = (const float*)d_in[5];
    const float* W3   = (const float*)d_in[6];
    const float* b3   = (const float*)d_in[7];
    const float* att1 = (const float*)d_in[8];
    const float* att2 = (const float*)d_in[9];
    const float* lw1  = (const float*)d_in[10];
    const float* lb1  = (const float*)d_in[11];
    const float* lw2  = (const float*)d_in[12];
    const float* lb2  = (const float*)d_in[13];
    const float* lw3  = (const float*)d_in[14];
    const float* lb3  = (const float*)d_in[15];
    float* out = (float*)d_out;
    int E = in_sizes[1]/2;

    float *adj1, *s, *u, *t1, *dis, *score, *xn1, *a1, *a2, *adj2, *t2, *xn2, *adj3, *t3;
    int* lidx;
    cudaGetSymbolAddress((void**)&adj1,  g_adj1);
    cudaGetSymbolAddress((void**)&s,     g_s);
    cudaGetSymbolAddress((void**)&u,     g_u);
    cudaGetSymbolAddress((void**)&t1,    g_t1);
    cudaGetSymbolAddress((void**)&dis,   g_dis);
    cudaGetSymbolAddress((void**)&score, g_score);
    cudaGetSymbolAddress((void**)&lidx,  g_lidx);
    cudaGetSymbolAddress((void**)&xn1,   g_xn1);
    cudaGetSymbolAddress((void**)&a1,    g_a1);
    cudaGetSymbolAddress((void**)&a2,    g_a2);
    cudaGetSymbolAddress((void**)&adj2,  g_adj2);
    cudaGetSymbolAddress((void**)&t2,    g_t2);
    cudaGetSymbolAddress((void**)&xn2,   g_xn2);
    cudaGetSymbolAddress((void**)&adj3,  g_adj3);
    cudaGetSymbolAddress((void**)&t3,    g_t3);

    // layer 1
    k_prep1    <<<NN1/8, 256>>>(x, W1, b1, adj1, s, u);
    k_scatter  <<<(E + 255)/256, 256>>>(ei, E, s, adj1);
    k_aggT<NPG1><<<NB*NPG1/32, 256>>>(adj1, u, t1, dis);
    k_scoreT<NPG1><<<NB*NPG1/32, 256>>>(adj1, t1, dis, score);
    k_topk     <<<NB, NPG1>>>(score, t1, att1, lidx, xn1, a1, a2, NPG1, KP1);
    k_adjbuild <<<NB*KP1, KP1>>>(a1, a2, lidx, adj1, adj2, NPG1, KP1);
    // layer 2
    k_linear   <<<NN2/8, 256>>>(xn1, W2, b2, u);
    k_aggT<KP1><<<NB*KP1/32, 256>>>(adj2, u, t2, dis);
    k_scoreT<KP1><<<NB*KP1/32, 256>>>(adj2, t2, dis, score);
    k_topk     <<<NB, KP1>>>(score, t2, att2, lidx, xn2, a1, a2, KP1, KP2);
    k_adjbuild <<<NB*KP2, KP2>>>(a1, a2, lidx, adj2, adj3, KP1, KP2);
    // layer 3
    k_linear   <<<NN3/8, 256>>>(xn2, W3, b3, u);
    k_aggT<KP2><<<NB*KP2/32, 256>>>(adj3, u, t3, dis);
    // readout + MLP
    k_final    <<<NB, 256>>>(xn1, xn2, t3, lw1, lb1, lw2, lb2, lw3, lb3, out);
}

// round 6
// speedup vs baseline: 3.1439x; 1.2188x over previous
#include <cuda_runtime.h>
#include <math.h>

#define NB     32
#define NPG1   256
#define NFEATD 128
#define NHID   64
#define KP1    128
#define KP2    64
#define NN1    (NB*NPG1)   // 8192
#define NN2    (NB*KP1)    // 4096
#define NN3    (NB*KP2)    // 2048
#define NCLS   6
#define PROJ_MAX 0.996f
#define MINN   1e-15f
#define AART   3.1063030f   // artanh(0.996)

// ---------------- device scratch ----------------
__device__ unsigned g_bm[NN1*8];        // layer-1 adjacency bitmap (256 bits/row)
__device__ float g_s[NN1];
__device__ float g_u[NN1*NHID];
__device__ float g_t1[NN1*NHID];
__device__ float g_dis[NN1];
__device__ float g_score[NN1];
__device__ float g_xn1[NN2*NHID];
__device__ float g_adj2[NB*KP1*KP1];
__device__ float g_t2[NN2*NHID];
__device__ float g_xn2[NN3*NHID];
__device__ float g_adj3[NB*KP2*KP2];
__device__ float g_t3[NN3*NHID];

// ---------------- helpers ----------------
__device__ __forceinline__ float artanh_(float x){
    x = fminf(fmaxf(x, -1.0f + 1e-7f), 1.0f - 1e-7f);
    return 0.5f*(log1pf(x) - log1pf(-x));
}
__device__ __forceinline__ float warpSum(float v){
    #pragma unroll
    for (int o = 16; o; o >>= 1) v += __shfl_xor_sync(0xffffffffu, v, o);
    return v;
}

// mobius tail: u = logmap0(proj(mobius_add(proj(expmap-scaled matvec), hb)))
__device__ __forceinline__ void hyp_tail(float mx0, float mx1, float xn,
                                         const float* __restrict__ bb, int l,
                                         float* __restrict__ up){
    float mxn = fmaxf(sqrtf(warpSum(mx0*mx0 + mx1*mx1)), MINN);
    float tv  = tanhf(mxn/xn*artanh_(xn));
    float hs  = tv/mxn;
    float h0 = mx0*hs, h1 = mx1*hs;
    float hn = tv;
    if (hn > PROJ_MAX){ float c = PROJ_MAX/hn; h0 *= c; h1 *= c; hn = PROJ_MAX; }
    float x2 = hn*hn;
    float b0 = bb[l], b1 = bb[l+32];
    float bn = fmaxf(sqrtf(warpSum(b0*b0 + b1*b1)), MINN);
    float tb = tanhf(bn);
    float hbs = tb/bn, hbn = tb;
    if (tb > PROJ_MAX){ hbs = PROJ_MAX/bn; hbn = PROJ_MAX; }
    float hb0 = b0*hbs, hb1 = b1*hbs;
    float y2 = hbn*hbn;
    float xy = warpSum(h0*hb0 + h1*hb1);
    float ca = 1.f + 2.f*xy + y2, cb = 1.f - x2;
    float den = fmaxf(1.f + 2.f*xy + x2*y2, MINN);
    float r0 = (ca*h0 + cb*hb0)/den, r1 = (ca*h1 + cb*hb1)/den;
    float rn = fmaxf(sqrtf(warpSum(r0*r0 + r1*r1)), MINN);
    float pn = rn, psc = 1.f;
    if (rn > PROJ_MAX){ psc = PROJ_MAX/rn; pn = PROJ_MAX; }
    float ls = artanh_(pn)/pn*psc;
    up[l] = r0*ls; up[l+32] = r1*ls;
}

// agg epilogue: logmap0(proj(expmap0(v))) == v*min(1,AART/||v||), then relu, again.
__device__ __forceinline__ void agg_epi(int node, float a0, float a1, float deg,
                                        float* __restrict__ tout, float* __restrict__ dis, int l){
    float n1 = sqrtf(warpSum(a0*a0 + a1*a1));
    float s1 = (n1 > AART) ? AART/n1 : 1.f;
    float w0 = fmaxf(a0*s1, 0.f), w1 = fmaxf(a1*s1, 0.f);
    float n2 = sqrtf(warpSum(w0*w0 + w1*w1));
    float s2 = (n2 > AART) ? AART/n2 : 1.f;
    tout[(size_t)node*64 + l]      = w0*s2;
    tout[(size_t)node*64 + l + 32] = w1*s2;
    if (l == 0) dis[node] = (deg > 0.f) ? rsqrtf(deg) : 0.f;
}

// ---------------- K1: zero bitmap + row sums + to_hyp + HypLinear (layer1) ----------------
__global__ void k_prep1(const float* __restrict__ x, const float* __restrict__ W1,
                        const float* __restrict__ bb, unsigned* __restrict__ bm,
                        float* __restrict__ s, float* __restrict__ u){
    __shared__ float Wt[128*64];
    int tid = threadIdx.x;
    if (tid < 64) bm[blockIdx.x*64 + tid] = 0u;   // 1024 blocks x 64 = 64K words
    for (int e = tid; e < 128*64; e += 256){
        int j = e >> 7, k = e & 127;
        Wt[k*64 + j] = W1[e];
    }
    __syncthreads();
    int w = tid >> 5, l = tid & 31;
    int node = blockIdx.x*8 + w;
    const float* xp = x + (size_t)node*128;
    float xq[4];
    #pragma unroll
    for (int q = 0; q < 4; q++) xq[q] = xp[l + 32*q];
    float ssum = warpSum(xq[0]+xq[1]+xq[2]+xq[3]);
    if (l == 0) s[node] = ssum;
    float n0 = fmaxf(sqrtf(warpSum(xq[0]*xq[0]+xq[1]*xq[1]+xq[2]*xq[2]+xq[3]*xq[3])), MINN);
    float th = tanhf(n0);
    float xsc, xn;
    if (th > PROJ_MAX){ xsc = PROJ_MAX/n0; xn = PROJ_MAX; } else { xsc = th/n0; xn = th; }
    xn = fmaxf(xn, MINN);
    #pragma unroll
    for (int q = 0; q < 4; q++) xq[q] *= xsc;
    float mx0 = 0.f, mx1 = 0.f;
    #pragma unroll
    for (int q = 0; q < 4; q++){
        float xv = xq[q];
        for (int kk = 0; kk < 32; kk++){
            float xk = __shfl_sync(0xffffffffu, xv, kk);
            int k = q*32 + kk;
            mx0 += xk*Wt[k*64 + l];
            mx1 += xk*Wt[k*64 + l + 32];
        }
    }
    hyp_tail(mx0, mx1, xn, bb, l, u + (size_t)node*64);
}

// ---------------- K2: edge scatter -> bitmap ----------------
__global__ void k_scatter(const int* __restrict__ ei, int E, unsigned* __restrict__ bm){
    int e = blockIdx.x*blockDim.x + threadIdx.x;
    if (e >= E) return;
    int r = ei[e], c = ei[E + e];
    int lc = c & 255;
    atomicOr(&bm[(size_t)r*8 + (lc >> 5)], 1u << (lc & 31));
}

// ---------------- K3: sparse layer-1 HypAgg (adj value = 0.5*(s_r+s_c)) ----------------
__global__ void k_agg1(const unsigned* __restrict__ bm, const float* __restrict__ s,
                       const float* __restrict__ u, float* __restrict__ tout,
                       float* __restrict__ dis){
    int w = threadIdx.x >> 5, l = threadIdx.x & 31;
    int node = blockIdx.x*8 + w;               // one warp per row
    int g = node >> 8;
    const float* ug = u + ((size_t)(g << 8))*64;
    const float* sg = s + (g << 8);
    float sn = sg[node & 255];
    float a0 = 0.f, a1 = 0.f, deg = 0.f;
    #pragma unroll
    for (int w8 = 0; w8 < 8; w8++){
        unsigned bits = bm[(size_t)node*8 + w8];
        while (bits){
            int b = __ffs(bits) - 1; bits &= bits - 1;
            int c = (w8 << 5) | b;
            float wv = 0.5f*(sn + sg[c]);
            a0 += wv*ug[(size_t)c*64 + l];
            a1 += wv*ug[(size_t)c*64 + l + 32];
            deg += wv;
        }
    }
    agg_epi(node, a0, a1, deg, tout, dis, l);
}

// ---------------- K4: sparse layer-1 node information score ----------------
__global__ void k_score1(const unsigned* __restrict__ bm, const float* __restrict__ s,
                         const float* __restrict__ t, const float* __restrict__ dis,
                         float* __restrict__ score){
    int w = threadIdx.x >> 5, l = threadIdx.x & 31;
    int node = blockIdx.x*8 + w;
    int g = node >> 8;
    const float* tg = t + ((size_t)(g << 8))*64;
    const float* sg = s + (g << 8);
    const float* dg = dis + (g << 8);
    float sn = sg[node & 255];
    float dn = dg[node & 255];
    float a0 = 0.f, a1 = 0.f;
    #pragma unroll
    for (int w8 = 0; w8 < 8; w8++){
        unsigned bits = bm[(size_t)node*8 + w8];
        while (bits){
            int b = __ffs(bits) - 1; bits &= bits - 1;
            int c = (w8 << 5) | b;
            float wv = 0.5f*(sn + sg[c])*dg[c];
            a0 += wv*tg[(size_t)c*64 + l];
            a1 += wv*tg[(size_t)c*64 + l + 32];
        }
    }
    float tr0 = tg[(size_t)(node & 255)*64 + l];
    float tr1 = tg[(size_t)(node & 255)*64 + l + 32];
    float d = fabsf(tr0 - dn*a0) + fabsf(tr1 - dn*a1);
    float sc = warpSum(d);
    if (l == 0) score[node] = sc;
}

// ---------------- K5a: layer-1 top-k + xn + att dots + adj2 build (fused) ----------------
__global__ void k_topk1(const float* __restrict__ score, const float* __restrict__ tin,
                        const float* __restrict__ att, const unsigned* __restrict__ bm,
                        const float* __restrict__ s,
                        float* __restrict__ xn, float* __restrict__ adj2){
    __shared__ float key[256];
    __shared__ int   idx[256];
    __shared__ float sa1[128], sa2[128], ss[256];
    __shared__ int   sli[128];
    int g = blockIdx.x, t = threadIdx.x;          // 256 threads
    key[t] = score[g*256 + t]; idx[t] = t; ss[t] = s[g*256 + t];
    for (int size = 2; size <= 256; size <<= 1){
        for (int stride = size >> 1; stride > 0; stride >>= 1){
            __syncthreads();
            int p = t ^ stride;
            if (p > t){
                float ka = key[t], kb = key[p];
                int ia = idx[t], ib = idx[p];
                bool before = (ka > kb) || (ka == kb && ia < ib);
                bool desc = ((t & size) == 0);
                if (desc ? !before : before){
                    key[t] = kb; key[p] = ka; idx[t] = ib; idx[p] = ia;
                }
            }
        }
    }
    __syncthreads();
    if (t < 128){
        int li = idx[t]; sli[t] = li;
        float tv = tanhf(key[t]);
        const float* src = tin + ((size_t)g*256 + li)*64;
        float* dst = xn + ((size_t)g*128 + t)*64;
        float d1 = 0.f, d2 = 0.f;
        #pragma unroll 8
        for (int j = 0; j < 64; j++){
            float v = src[j]*tv; dst[j] = v;
            d1 += v*att[j]; d2 += v*att[64 + j];
        }
        sa1[t] = d1; sa2[t] = d2;
    }
    __syncthreads();
    const unsigned* bmg = bm + (size_t)g*256*8;
    for (int e = t; e < 128*128; e += 256){
        int i = e >> 7, j = e & 127;
        float ev = fmaxf(sa1[i] + sa2[j], 0.f);   // relu(leaky_relu(e)) == relu(e)
        int li = sli[i], lj = sli[j];
        unsigned word = bmg[li*8 + (lj >> 5)];
        float old = ((word >> (lj & 31)) & 1u) ? 0.5f*(ss[li] + ss[lj]) : 0.f;
        adj2[((size_t)g*128 + i)*128 + j] = ev + old;
    }
}

// ---------------- K5b: layer-2 top-k + adj3 build (dense oldadj) ----------------
__global__ void k_topk2(const float* __restrict__ score, const float* __restrict__ tin,
                        const float* __restrict__ att, const float* __restrict__ oldadj,
                        float* __restrict__ xn, float* __restrict__ adj3){
    __shared__ float key[128];
    __shared__ int   idx[128];
    __shared__ float sa1[64], sa2[64];
    __shared__ int   sli[64];
    int g = blockIdx.x, t = threadIdx.x;          // 128 threads
    key[t] = score[g*128 + t]; idx[t] = t;
    for (int size = 2; size <= 128; size <<= 1){
        for (int stride = size >> 1; stride > 0; stride >>= 1){
            __syncthreads();
            int p = t ^ stride;
            if (p > t){
                float ka = key[t], kb = key[p];
                int ia = idx[t], ib = idx[p];
                bool before = (ka > kb) || (ka == kb && ia < ib);
                bool desc = ((t & size) == 0);
                if (desc ? !before : before){
                    key[t] = kb; key[p] = ka; idx[t] = ib; idx[p] = ia;
                }
            }
        }
    }
    __syncthreads();
    if (t < 64){
        int li = idx[t]; sli[t] = li;
        float tv = tanhf(key[t]);
        const float* src = tin + ((size_t)g*128 + li)*64;
        float* dst = xn + ((size_t)g*64 + t)*64;
        float d1 = 0.f, d2 = 0.f;
        #pragma unroll 8
        for (int j = 0; j < 64; j++){
            float v = src[j]*tv; dst[j] = v;
            d1 += v*att[j]; d2 += v*att[64 + j];
        }
        sa1[t] = d1; sa2[t] = d2;
    }
    __syncthreads();
    const float* oag = oldadj + (size_t)g*128*128;
    for (int e = t; e < 64*64; e += 128){
        int i = e >> 6, j = e & 63;
        float ev = fmaxf(sa1[i] + sa2[j], 0.f);
        adj3[((size_t)g*64 + i)*64 + j] = ev + oag[(size_t)sli[i]*128 + sli[j]];
    }
}

// ---------------- K7: to_hyp + HypLinear, 64-dim ----------------
__global__ void k_linear(const float* __restrict__ xin, const float* __restrict__ W,
                         const float* __restrict__ bb, float* __restrict__ u){
    __shared__ float Wt[64*64];
    int tid = threadIdx.x;
    for (int e = tid; e < 4096; e += 256){
        int j = e >> 6, k = e & 63;
        Wt[k*64 + j] = W[e];
    }
    __syncthreads();
    int w = tid >> 5, l = tid & 31;
    int node = blockIdx.x*8 + w;
    const float* xp = xin + (size_t)node*64;
    float x0 = xp[l], x1 = xp[l+32];
    float n0 = fmaxf(sqrtf(warpSum(x0*x0 + x1*x1)), MINN);
    float th = tanhf(n0);
    float xsc, xn;
    if (th > PROJ_MAX){ xsc = PROJ_MAX/n0; xn = PROJ_MAX; } else { xsc = th/n0; xn = th; }
    xn = fmaxf(xn, MINN);
    x0 *= xsc; x1 *= xsc;
    float mx0 = 0.f, mx1 = 0.f;
    #pragma unroll
    for (int q = 0; q < 2; q++){
        float xv = q ? x1 : x0;
        for (int kk = 0; kk < 32; kk++){
            float xk = __shfl_sync(0xffffffffu, xv, kk);
            int k = q*32 + kk;
            mx0 += xk*Wt[k*64 + l];
            mx1 += xk*Wt[k*64 + l + 32];
        }
    }
    hyp_tail(mx0, mx1, xn, bb, l, u + (size_t)node*64);
}

// ---------------- dense HypAgg, 2 rows/warp, single smem chunk ----------------
template<int NPG>
__global__ void k_aggT(const float* __restrict__ adj, const float* __restrict__ u,
                       float* __restrict__ tout, float* __restrict__ dis){
    constexpr int TPG = NPG/16;
    __shared__ float ush[NPG*64];
    int g = blockIdx.x / TPG, rt = blockIdx.x % TPG;
    int w = threadIdx.x >> 5, l = threadIdx.x & 31;
    int rbase = rt*16 + w*2;
    const float* adjg = adj + (size_t)g*NPG*NPG;
    const float* ug   = u   + (size_t)g*NPG*64;
    {
        const float4* src = (const float4*)ug;
        float4* dst = (float4*)ush;
        for (int e = threadIdx.x; e < NPG*16; e += 256) dst[e] = src[e];
    }
    __syncthreads();
    const float* r0p = adjg + (size_t)rbase*NPG;
    const float* r1p = r0p + NPG;
    float a00=0,a01=0,a10=0,a11=0,d0=0,d1=0;
    #pragma unroll 4
    for (int m = 0; m < NPG; m += 4){
        float4 v0 = *(const float4*)(r0p + m);
        float4 v1 = *(const float4*)(r1p + m);
        float ar0[4] = {v0.x, v0.y, v0.z, v0.w};
        float ar1[4] = {v1.x, v1.y, v1.z, v1.w};
        #pragma unroll
        for (int q = 0; q < 4; q++){
            float u0 = ush[(m+q)*64 + l];
            float u1 = ush[(m+q)*64 + l + 32];
            a00 += ar0[q]*u0; a01 += ar0[q]*u1; d0 += ar0[q];
            a10 += ar1[q]*u0; a11 += ar1[q]*u1; d1 += ar1[q];
        }
    }
    int nb = g*NPG + rbase;
    agg_epi(nb,   a00, a01, d0, tout, dis, l);
    agg_epi(nb+1, a10, a11, d1, tout, dis, l);
}

// ---------------- dense node information score, 2 rows/warp ----------------
template<int NPG>
__global__ void k_scoreT(const float* __restrict__ adj, const float* __restrict__ t,
                         const float* __restrict__ dis, float* __restrict__ score){
    constexpr int TPG = NPG/16;
    __shared__ float tsh[NPG*64];
    int g = blockIdx.x / TPG, rt = blockIdx.x % TPG;
    int w = threadIdx.x >> 5, l = threadIdx.x & 31;
    int rbase = rt*16 + w*2;
    const float* adjg = adj + (size_t)g*NPG*NPG;
    const float* tg   = t   + (size_t)g*NPG*64;
    const float* disg = dis + (size_t)g*NPG;
    {
        const float4* src = (const float4*)tg;
        float4* dst = (float4*)tsh;
        for (int e = threadIdx.x; e < NPG*16; e += 256){
            float4 v = src[e];
            float dm = disg[e >> 4];
            v.x *= dm; v.y *= dm; v.z *= dm; v.w *= dm;
            dst[e] = v;
        }
    }
    float tr0 = tg[(size_t)rbase*64 + l],     tr1 = tg[(size_t)rbase*64 + l + 32];
    float sr0 = tg[(size_t)(rbase+1)*64 + l], sr1 = tg[(size_t)(rbase+1)*64 + l + 32];
    float dr0 = disg[rbase], dr1 = disg[rbase+1];
    __syncthreads();
    const float* r0p = adjg + (size_t)rbase*NPG;
    const float* r1p = r0p + NPG;
    float a00=0,a01=0,a10=0,a11=0;
    #pragma unroll 4
    for (int m = 0; m < NPG; m += 4){
        float4 v0 = *(const float4*)(r0p + m);
        float4 v1 = *(const float4*)(r1p + m);
        float ar0[4] = {v0.x, v0.y, v0.z, v0.w};
        float ar1[4] = {v1.x, v1.y, v1.z, v1.w};
        #pragma unroll
        for (int q = 0; q < 4; q++){
            float u0 = tsh[(m+q)*64 + l];
            float u1 = tsh[(m+q)*64 + l + 32];
            a00 += ar0[q]*u0; a01 += ar0[q]*u1;
            a10 += ar1[q]*u0; a11 += ar1[q]*u1;
        }
    }
    float d0 = fabsf(tr0 - dr0*a00) + fabsf(tr1 - dr0*a01);
    float d1 = fabsf(sr0 - dr1*a10) + fabsf(sr1 - dr1*a11);
    float sc0 = warpSum(d0), sc1 = warpSum(d1);
    if (l == 0){ score[g*NPG + rbase] = sc0; score[g*NPG + rbase + 1] = sc1; }
}

// ---------------- K8: readouts + MLP head + log_softmax ----------------
__global__ void k_final(const float* __restrict__ xn1, const float* __restrict__ xn2,
                        const float* __restrict__ t3,
                        const float* __restrict__ lw1, const float* __restrict__ lb1,
                        const float* __restrict__ lw2, const float* __restrict__ lb2,
                        const float* __restrict__ lw3, const float* __restrict__ lb3,
                        float* __restrict__ out){
    __shared__ float sA[4*64], sB[4*64], rr[128], h1[64], h2[32], lg[NCLS];
    int g = blockIdx.x, t = threadIdx.x;
    int f = t & 63, grp = t >> 6;
    float accM = 0.f, accE = 0.f;
    #pragma unroll
    for (int srci = 0; srci < 3; srci++){
        const float* base = (srci == 0) ? xn1 + (size_t)g*KP1*64
                          : (srci == 1) ? xn2 + (size_t)g*KP2*64
                                        : t3  + (size_t)g*KP2*64;
        int K = (srci == 0) ? KP1 : KP2;
        float pm = -3.402823466e38f, ps = 0.f;
        for (int i = grp; i < K; i += 4){
            float v = base[(size_t)i*64 + f];
            pm = fmaxf(pm, v); ps += v;
        }
        sA[grp*64 + f] = pm; sB[grp*64 + f] = ps;
        __syncthreads();
        if (t < 64){
            float mx = fmaxf(fmaxf(sA[f], sA[64+f]), fmaxf(sA[128+f], sA[192+f]));
            float sm = sB[f] + sB[64+f] + sB[128+f] + sB[192+f];
            accM += fmaxf(mx, 0.f);
            accE += fmaxf(sm/(float)K, 0.f);
        }
        __syncthreads();
    }
    if (t < 64){ rr[f] = accM; rr[64+f] = accE; }
    __syncthreads();
    if (t < 64){
        float a = lb1[t];
        #pragma unroll 8
        for (int q = 0; q < 128; q++) a += lw1[(size_t)t*128 + q]*rr[q];
        h1[t] = fmaxf(a, 0.f);
    }
    __syncthreads();
    if (t < 32){
        float a = lb2[t];
        #pragma unroll 8
        for (int q = 0; q < 64; q++) a += lw2[(size_t)t*64 + q]*h1[q];
        h2[t] = fmaxf(a, 0.f);
    }
    __syncthreads();
    if (t < NCLS){
        float a = lb3[t];
        #pragma unroll
        for (int q = 0; q < 32; q++) a += lw3[(size_t)t*32 + q]*h2[q];
        lg[t] = a;
    }
    __syncthreads();
    if (t == 0){
        float mx = lg[0];
        for (int c = 1; c < NCLS; c++) mx = fmaxf(mx, lg[c]);
        float sm = 0.f;
        for (int c = 0; c < NCLS; c++) sm += expf(lg[c] - mx);
        float lse = mx + logf(sm);
        for (int c = 0; c < NCLS; c++) out[g*NCLS + c] = lg[c] - lse;
    }
}

// ---------------- host launcher ----------------
extern "C" void kernel_launch(void* const* d_in, const int* in_sizes, int n_in,
                              void* d_out, int out_size){
    const float* x    = (const float*)d_in[0];
    const int*   ei   = (const int*)  d_in[1];
    const float* W1   = (const float*)d_in[2];
    const float* b1   = (const float*)d_in[3];
    const float* W2   = (const float*)d_in[4];
    const float* b2   = (const float*)d_in[5];
    const float* W3   = (const float*)d_in[6];
    const float* b3   = (const float*)d_in[7];
    const float* att1 = (const float*)d_in[8];
    const float* att2 = (const float*)d_in[9];
    const float* lw1  = (const float*)d_in[10];
    const float* lb1  = (const float*)d_in[11];
    const float* lw2  = (const float*)d_in[12];
    const float* lb2  = (const float*)d_in[13];
    const float* lw3  = (const float*)d_in[14];
    const float* lb3  = (const float*)d_in[15];
    float* out = (float*)d_out;
    int E = in_sizes[1]/2;

    unsigned* bm; float *s, *u, *t1, *dis, *score, *xn1, *adj2, *t2, *xn2, *adj3, *t3;
    cudaGetSymbolAddress((void**)&bm,    g_bm);
    cudaGetSymbolAddress((void**)&s,     g_s);
    cudaGetSymbolAddress((void**)&u,     g_u);
    cudaGetSymbolAddress((void**)&t1,    g_t1);
    cudaGetSymbolAddress((void**)&dis,   g_dis);
    cudaGetSymbolAddress((void**)&score, g_score);
    cudaGetSymbolAddress((void**)&xn1,   g_xn1);
    cudaGetSymbolAddress((void**)&adj2,  g_adj2);
    cudaGetSymbolAddress((void**)&t2,    g_t2);
    cudaGetSymbolAddress((void**)&xn2,   g_xn2);
    cudaGetSymbolAddress((void**)&adj3,  g_adj3);
    cudaGetSymbolAddress((void**)&t3,    g_t3);

    // layer 1 (sparse)
    k_prep1   <<<NN1/8, 256>>>(x, W1, b1, bm, s, u);
    k_scatter <<<(E + 255)/256, 256>>>(ei, E, bm);
    k_agg1    <<<NN1/8, 256>>>(bm, s, u, t1, dis);
    k_score1  <<<NN1/8, 256>>>(bm, s, t1, dis, score);
    k_topk1   <<<NB, 256>>>(score, t1, att1, bm, s, xn1, adj2);
    // layer 2 (dense 128)
    k_linear  <<<NN2/8, 256>>>(xn1, W2, b2, u);
    k_aggT<KP1>  <<<NB*KP1/16, 256>>>(adj2, u, t2, dis);
    k_scoreT<KP1><<<NB*KP1/16, 256>>>(adj2, t2, dis, score);
    k_topk2   <<<NB, 128>>>(score, t2, att2, adj2, xn2, adj3);
    // layer 3 (dense 64)
    k_linear  <<<NN3/8, 256>>>(xn2, W3, b3, u);
    k_aggT<KP2><<<NB*KP2/16, 256>>>(adj3, u, t3, dis);
    // readout + MLP
    k_final   <<<NB, 256>>>(xn1, xn2, t3, lw1, lb1, lw2, lb2, lw3, lb3, out);
}